// round 17
// baseline (speedup 1.0000x reference)
#include <cuda_runtime.h>
#include <cuda_fp16.h>

// GenerateNodes via pure-fp16 mma.sync (HMMA) GEMM — compute_103-safe.
//   out[m, o*20+node] = sum_c mix[m,c] * W[node*3+o, c] + b[node*3+o]
//   mix = concat(x[m,0:3200], seeds[m,0:15]);
//   A = fp16(mix), W = fp16(W), fp32 accumulate. rel_err ~3e-4 (<1e-3).
// R15: fully-async x path — 3-stage cp.async fp32 staging (distance-2),
//      smem->smem convert, no register prefetch. k-split warp tiling (R14).

#define NROWS   16384
#define KX      3200
#define KS      15
#define KTOT    3215
#define KPAD    3328      // 26 * 128
#define NCH     25        // full x chunks of 128; chunk 25 = seeds
#define JDIM    60
#define JPAD    64
#define MT      32        // rows per CTA
#define THREADS 128

#define A_SUB   4096              // 32 rows x 64 fp16 (128 B, SW128)
#define B_SUB   8192              // 64 j x 64 fp16
#define XS_TILE 16384             // 32 rows x 128 fp32 staging (512 B/row)
#define W_TILE  16384             // 2 k-block B sub-tiles
#define XS_OFF(s) ((s) * XS_TILE)
#define W_OFF(s)  (3 * XS_TILE + (s) * W_TILE)
#define A_OFF(s)  (3 * XS_TILE + 3 * W_TILE + (s) * 2 * A_SUB)
#define SMEM_SZ   (3 * XS_TILE + 3 * W_TILE + 2 * 2 * A_SUB)   // 114688

__device__ __align__(16) __half g_Wh[JPAD * KPAD];

// ------------------------- helpers -------------------------
__device__ __forceinline__ unsigned s2u(const void* p) {
    unsigned a;
    asm("{ .reg .u64 t; cvta.to.shared.u64 t, %1; cvt.u32.u64 %0, t; }"
        : "=r"(a) : "l"(p));
    return a;
}
__device__ __forceinline__ unsigned swz(unsigned off) {
    return off ^ ((off >> 3) & 0x70);
}
__device__ __forceinline__ unsigned pack_h(float a, float b) {
    unsigned short ra = __half_as_ushort(__float2half_rn(a));
    unsigned short rb = __half_as_ushort(__float2half_rn(b));
    return (unsigned)ra | ((unsigned)rb << 16);
}
__device__ __forceinline__ void ldsm4(unsigned addr, unsigned& r0, unsigned& r1,
                                      unsigned& r2, unsigned& r3) {
    asm volatile("ldmatrix.sync.aligned.m8n8.x4.shared.b16 {%0,%1,%2,%3}, [%4];"
                 : "=r"(r0), "=r"(r1), "=r"(r2), "=r"(r3) : "r"(addr));
}
__device__ __forceinline__ void mmaf16(float* c, unsigned a0, unsigned a1,
                                       unsigned a2, unsigned a3,
                                       unsigned b0, unsigned b1) {
    asm volatile(
        "mma.sync.aligned.m16n8k16.row.col.f32.f16.f16.f32 "
        "{%0,%1,%2,%3}, {%4,%5,%6,%7}, {%8,%9}, {%0,%1,%2,%3};"
        : "+f"(c[0]), "+f"(c[1]), "+f"(c[2]), "+f"(c[3])
        : "r"(a0), "r"(a1), "r"(a2), "r"(a3), "r"(b0), "r"(b1));
}
__device__ __forceinline__ void cpasync16(unsigned dst, const void* src) {
    asm volatile("cp.async.cg.shared.global [%0], [%1], 16;"
                 :: "r"(dst), "l"(src) : "memory");
}

// ------------------ kernel 1: W -> fp16 ------------------
__global__ void prep_W_kernel(const float* __restrict__ W) {
    int idx = blockIdx.x * 256 + threadIdx.x;
    if (idx >= JPAD * KPAD) return;
    int j = idx / KPAD;
    int c = idx - j * KPAD;
    float v = (j < JDIM && c < KTOT) ? W[(size_t)j * KTOT + c] : 0.0f;
    g_Wh[idx] = __float2half_rn(v);
}

// ------------------------- main GEMM kernel -------------------------
__global__ __launch_bounds__(THREADS, 2)
void mma_kernel(const float* __restrict__ x, const float* __restrict__ seeds,
                const float* __restrict__ bias, float* __restrict__ out)
{
    extern __shared__ char smem[];
    const unsigned sb = s2u(smem);
    const int tid  = threadIdx.x;
    const int lane = tid & 31;
    const int warp = tid >> 5;            // 4 warps
    const int kh   = warp >> 1;           // k-half: kb sub-tile kh
    const int nh   = warp & 1;            // n-half: cols 32nh..32nh+31
    const int row0 = blockIdx.x * MT;

    // ldmatrix lane geometry (A covers rows 0..31 via mb loop)
    const int amat  = lane >> 3;
    const int arow0 = 8 * (amat & 1) + (lane & 7);   // + 16*mb
    const int acolb = (amat >> 1) * 16;              // byte offset within k16
    const int brow  = (lane & 7);
    const int bnt   = (lane >> 4) & 1;               // ntile within pair
    const int bkb   = ((lane >> 3) & 1) * 16;        // byte k-offset

    // x tile mapping: warp w handles rows {w, w+4, ..., w+28}; lane = 16B col
    const int xrw = tid >> 5;             // base row (0..3); row_i = xrw + 4i
    const int xq  = tid & 31;             // 16B-col 0..31
    const int xkb = xq >> 4;              // k-block of this thread's column
    const int xq64 = xq & 15;
    // W tile per k-block = 64 j x 8 slots of 16B = 512; 4 iters of 128 thr
    const int wj[4] = { tid >> 3, (tid + 128) >> 3, (tid + 256) >> 3, (tid + 384) >> 3 };
    const int wqq = tid & 7;

    // acc[4*mb + nt][4]: mb in {0,1} row-band, nt in {0..3} n8-tile
    float acc[8][4];
    #pragma unroll
    for (int n = 0; n < 8; n++)
        #pragma unroll
        for (int q = 0; q < 4; q++) acc[n][q] = 0.0f;

    // cp.async x fp32 chunk -> staging stage s (linear 512 B/row layout)
    #define CPX(ch, s) { _Pragma("unroll") \
        for (int i = 0; i < 8; i++) { \
            const int r = xrw + 4 * i; \
            cpasync16(sb + XS_OFF(s) + (unsigned)(r * 512 + 16 * xq), \
                      x + (size_t)(row0 + r) * KX + (ch) * 128 + 4 * xq); } }
    #define CPW(ch, s) { _Pragma("unroll") \
        for (int kb = 0; kb < 2; kb++) { \
            _Pragma("unroll") \
            for (int i = 0; i < 4; i++) { \
                const unsigned so = (unsigned)(kb * B_SUB) + swz((unsigned)(wj[i] * 128 + 16 * wqq)); \
                cpasync16(sb + W_OFF(s) + so, \
                          &g_Wh[(size_t)wj[i] * KPAD + (ch) * 128 + kb * 64 + 8 * wqq]); \
            } \
        } }
    #define COMMIT() asm volatile("cp.async.commit_group;" ::: "memory")

    // smem fp32 -> swizzled fp16 A tile (reads exactly this thread's cp.async bytes)
    #define CONVERT(sx, sa) { _Pragma("unroll") \
        for (int i = 0; i < 8; i++) { \
            const int r = xrw + 4 * i; \
            const float4 v = *reinterpret_cast<const float4*>( \
                smem + XS_OFF(sx) + r * 512 + 16 * xq); \
            const unsigned off = (unsigned)(xkb * A_SUB) + \
                swz((unsigned)(r * 128 + 8 * xq64)); \
            const unsigned long long pp = (unsigned long long)pack_h(v.x, v.y) | \
                ((unsigned long long)pack_h(v.z, v.w) << 32); \
            *reinterpret_cast<unsigned long long*>(smem + A_OFF(sa) + off) = pp; } }

    // Each warp: its kh sub-tile only; rows 0..31 (mb loop), cols 32nh..+31.
    #define COMPUTE(sa, sw) { \
        const unsigned aB = sb + A_OFF(sa) + (unsigned)(kh * A_SUB); \
        const unsigned bB = sb + W_OFF(sw) + (unsigned)(kh * B_SUB); \
        _Pragma("unroll") \
        for (int kl = 0; kl < 4; kl++) { \
            unsigned a0[2][4]; \
            _Pragma("unroll") \
            for (int mb = 0; mb < 2; mb++) { \
                const unsigned aoff = swz((unsigned)( \
                    (16 * mb + arow0) * 128 + 32 * kl + acolb)); \
                ldsm4(aB + aoff, a0[mb][0], a0[mb][1], a0[mb][2], a0[mb][3]); \
            } \
            _Pragma("unroll") \
            for (int ntp = 0; ntp < 2; ntp++) { \
                const unsigned boff = swz((unsigned)( \
                    (8 * (4 * nh + 2 * ntp + bnt) + brow) * 128 + 32 * kl + bkb)); \
                unsigned b0, b1, b2, b3; \
                ldsm4(bB + boff, b0, b1, b2, b3); \
                _Pragma("unroll") \
                for (int mb = 0; mb < 2; mb++) { \
                    mmaf16(acc[4 * mb + 2 * ntp],     a0[mb][0], a0[mb][1], a0[mb][2], a0[mb][3], b0, b1); \
                    mmaf16(acc[4 * mb + 2 * ntp + 1], a0[mb][0], a0[mb][1], a0[mb][2], a0[mb][3], b2, b3); \
                } \
            } \
        } }

    // ---------------- pipeline: 3-stage ring, distance-2 groups ----------------
    CPX(0, 0); CPW(0, 0); COMMIT();
    CPX(1, 1); CPW(1, 1); COMMIT();

    for (int ch = 0; ch < NCH; ch++) {
        const int s3 = ch % 3, sa = ch & 1;
        asm volatile("cp.async.wait_group 1;" ::: "memory");  // group(ch) arrived
        CONVERT(s3, sa);                 // own-thread bytes: no barrier needed
        __syncthreads();                 // A(sa) visible; stage (ch+2)%3 free
        const int ch2 = ch + 2;
        if (ch2 < NCH)       { const int t3 = ch2 % 3; CPX(ch2, t3); CPW(ch2, t3); COMMIT(); }
        else if (ch2 == NCH) { CPW(NCH, NCH % 3); COMMIT(); }   // seeds W only
        COMPUTE(sa, s3);
    }

    // ---- seeds chunk (ch = 25): A stage 1, W stage 25%3 = 1 ----
    asm volatile("cp.async.wait_group 0;" ::: "memory");       // W(25) arrived
    for (int i = tid; i < (2 * A_SUB) / 16; i += THREADS)
        *reinterpret_cast<uint4*>(smem + A_OFF(1) + 16 * i) = make_uint4(0, 0, 0, 0);
    __syncthreads();                                           // zeros visible
    for (int i = tid; i < MT * KS; i += THREADS) {
        const int r = i / KS, c = i - r * KS;
        const float v = seeds[(size_t)(row0 + r) * KS + c];
        const unsigned off = swz((unsigned)(r * 128 + 2 * c));   // kb 0 (c < 64)
        *reinterpret_cast<__half*>(smem + A_OFF(1) + off) = __float2half_rn(v);
    }
    __syncthreads();
    COMPUTE(1, 1);
    // (kh=1 warps multiply zeroed kb=1 sub-tiles: harmless.)

    // ---- epilogue: deterministic k-reduction, then permuted+bias store ----
    __syncthreads();                                           // all computes done
    float* red = reinterpret_cast<float*>(smem);               // [32][68] in XS(0)
    const int g = lane >> 2, t = lane & 3;
    if (kh == 0) {
        #pragma unroll
        for (int mb = 0; mb < 2; mb++)
            #pragma unroll
            for (int nt = 0; nt < 4; nt++) {
                const int col = 32 * nh + 8 * nt + 2 * t;
                red[(16 * mb + g)     * 68 + col]     = acc[4 * mb + nt][0];
                red[(16 * mb + g)     * 68 + col + 1] = acc[4 * mb + nt][1];
                red[(16 * mb + 8 + g) * 68 + col]     = acc[4 * mb + nt][2];
                red[(16 * mb + 8 + g) * 68 + col + 1] = acc[4 * mb + nt][3];
            }
    }
    __syncthreads();
    if (kh == 1) {
        #pragma unroll
        for (int mb = 0; mb < 2; mb++)
            #pragma unroll
            for (int nt = 0; nt < 4; nt++) {
                const int col = 32 * nh + 8 * nt + 2 * t;
                red[(16 * mb + g)     * 68 + col]     += acc[4 * mb + nt][0];
                red[(16 * mb + g)     * 68 + col + 1] += acc[4 * mb + nt][1];
                red[(16 * mb + 8 + g) * 68 + col]     += acc[4 * mb + nt][2];
                red[(16 * mb + 8 + g) * 68 + col + 1] += acc[4 * mb + nt][3];
            }
    }
    __syncthreads();
    for (int i = tid; i < MT * JDIM; i += THREADS) {
        const int r = i / JDIM, pos = i - r * JDIM;
        const int o = pos / 20, node = pos - 20 * o;
        const int j = node * 3 + o;
        out[(size_t)row0 * JDIM + i] = red[r * 68 + j] + bias[j];
    }
}

extern "C" void kernel_launch(void* const* d_in, const int* in_sizes, int n_in,
                              void* d_out, int out_size)
{
    const float* x     = (const float*)d_in[0];
    const float* seeds = (const float*)d_in[1];
    const float* W     = (const float*)d_in[2];
    const float* b     = (const float*)d_in[3];
    float*       out   = (float*)d_out;

    cudaFuncSetAttribute(mma_kernel,
                         cudaFuncAttributeMaxDynamicSharedMemorySize, SMEM_SZ);
    prep_W_kernel<<<(JPAD * KPAD + 255) / 256, 256>>>(W);
    mma_kernel<<<NROWS / MT, THREADS, SMEM_SZ>>>(x, seeds, b, out);
}